// round 1
// baseline (speedup 1.0000x reference)
#include <cuda_runtime.h>

#define TPB 256
#define MAXN 256   // max gt boxes per image supported

// Scratch (device globals; no allocation allowed)
__device__ unsigned long long g_partial[1 << 19];  // per-(b,n) per-chunk best keys
__device__ unsigned long long g_abest[1 << 20];    // per-(b,a) packed (iou, box idx)
__device__ int                g_winner[1 << 20];   // per-(b,a) segment_max winner
__device__ float              g_miou[8192];        // per-(b,n) max iou over anchors

__device__ __forceinline__ unsigned long long pack_key(float iou, int anchor_idx) {
    // max key -> max iou, tie -> lowest anchor idx (JAX argmax first-occurrence)
    return ((unsigned long long)__float_as_uint(iou) << 32) |
           (unsigned long long)(0xFFFFFFFFu - (unsigned)anchor_idx);
}

// K1: for each (batch, anchor-chunk): compute all IoUs vs N boxes once.
//  - per-anchor best (axis=1 argmax, strict > = first occurrence) -> g_abest
//  - per-box block-best (axis=0 argmax candidate) -> g_partial
//  - init g_winner = -1
__global__ void __launch_bounds__(TPB)
k_phase1(const float4* __restrict__ anchors, const float4* __restrict__ bboxes,
         int A, int N, int numChunks)
{
    __shared__ float4 sbox[MAXN];
    __shared__ float  sarea[MAXN];
    __shared__ unsigned long long swb[MAXN * 8];

    const int b = blockIdx.y, chunk = blockIdx.x, tid = threadIdx.x;
    const int lane = tid & 31, wid = tid >> 5;

    for (int n = tid; n < N; n += TPB) {
        float4 bb = bboxes[b * N + n];
        sbox[n] = bb;
        sarea[n] = (bb.z - bb.x) * (bb.w - bb.y);
    }
    __syncthreads();

    const int a = chunk * TPB + tid;
    const bool valid = (a < A);
    float ax1 = 0.f, ay1 = 0.f, ax2 = 0.f, ay2 = 0.f, areaA = 0.f;
    if (valid) {
        float4 c = anchors[a];
        ax1 = c.x - c.z * 0.5f;  ay1 = c.y - c.w * 0.5f;
        ax2 = c.x + c.z * 0.5f;  ay2 = c.y + c.w * 0.5f;
        areaA = (ax2 - ax1) * (ay2 - ay1);          // matches reference order
        g_winner[b * A + a] = -1;
    }

    float bestI = -1.0f; int bestN = 0;
    for (int n = 0; n < N; n++) {
        float4 bb = sbox[n];
        float ltx = fmaxf(ax1, bb.x), lty = fmaxf(ay1, bb.y);
        float rbx = fminf(ax2, bb.z), rby = fminf(ay2, bb.w);
        float w = fmaxf(rbx - ltx, 0.f), h = fmaxf(rby - lty, 0.f);
        float inter = w * h;
        float iou = inter / (areaA + sarea[n] - inter);

        unsigned long long key = valid ? pack_key(iou, a) : 0ull;
        if (valid && iou > bestI) { bestI = iou; bestN = n; }

        #pragma unroll
        for (int off = 16; off; off >>= 1) {
            unsigned long long o = __shfl_down_sync(0xffffffffu, key, off);
            if (o > key) key = o;
        }
        if (lane == 0) swb[n * 8 + wid] = key;
    }

    if (valid)
        g_abest[(size_t)b * A + a] =
            ((unsigned long long)__float_as_uint(bestI) << 32) | (unsigned)bestN;

    __syncthreads();
    for (int n = tid; n < N; n += TPB) {
        unsigned long long best = swb[n * 8];
        #pragma unroll
        for (int w8 = 1; w8 < 8; w8++)
            if (swb[n * 8 + w8] > best) best = swb[n * 8 + w8];
        g_partial[((size_t)(b * N + n)) * numChunks + chunk] = best;
    }
}

// K2: reduce chunk partials per (b,n) -> max_iou_of_bbox + anchor argmax,
//     then segment_max scatter: winner[anchor] = max n claiming it.
__global__ void __launch_bounds__(TPB)
k_phase2(int A, int N, int numChunks)
{
    const int bn = blockIdx.x, tid = threadIdx.x;
    const int lane = tid & 31, wid = tid >> 5;
    const unsigned long long* p = g_partial + (size_t)bn * numChunks;

    unsigned long long key = 0;
    for (int c = tid; c < numChunks; c += TPB) {
        unsigned long long v = p[c];
        if (v > key) key = v;
    }
    __shared__ unsigned long long sred[8];
    #pragma unroll
    for (int off = 16; off; off >>= 1) {
        unsigned long long o = __shfl_down_sync(0xffffffffu, key, off);
        if (o > key) key = o;
    }
    if (lane == 0) sred[wid] = key;
    __syncthreads();
    if (wid == 0) {
        key = (lane < 8) ? sred[lane] : 0ull;
        #pragma unroll
        for (int off = 4; off; off >>= 1) {
            unsigned long long o = __shfl_down_sync(0xffffffffu, key, off);
            if (o > key) key = o;
        }
        if (lane == 0) {
            float miou = __uint_as_float((unsigned)(key >> 32));
            int   idx  = (int)(0xFFFFFFFFu - (unsigned)key);
            g_miou[bn] = miou;
            int b = bn / N, n = bn - b * N;
            atomicMax(&g_winner[(size_t)b * A + idx], n);
        }
    }
}

// K3: epilogue per anchor: winner override, scores, conf scatter, delta encode.
__global__ void __launch_bounds__(TPB)
k_phase3(const float4* __restrict__ anchors, const float4* __restrict__ bboxes,
         const int* __restrict__ labels,
         const float* __restrict__ enc_mean, const float* __restrict__ enc_std,
         const float* __restrict__ thr_ptr,
         float* __restrict__ out_conf, float4* __restrict__ out_delta,
         int A, int N, int C)
{
    __shared__ float4 sbox[MAXN];
    __shared__ int    slab[MAXN];
    __shared__ float  smiou[MAXN];

    const int b = blockIdx.y, tid = threadIdx.x;
    for (int n = tid; n < N; n += TPB) {
        sbox[n]  = bboxes[b * N + n];
        slab[n]  = labels[b * N + n];
        smiou[n] = g_miou[b * N + n];
    }
    __syncthreads();

    const int a = blockIdx.x * TPB + tid;
    if (a >= A) return;

    const float thr = __ldg(thr_ptr);
    unsigned long long ab = g_abest[(size_t)b * A + a];
    float miou = __uint_as_float((unsigned)(ab >> 32));
    int   idx  = (int)(unsigned)ab;

    int w = g_winner[(size_t)b * A + a];
    if (w >= 0) { idx = w; miou = smiou[w]; }

    float den = fmaxf(smiou[idx], thr);
    if (miou < thr * 0.5f) miou = 0.f;
    float score = miou / den;

    int lab = slab[idx];
    if (lab <= 0) { score = 0.f; lab = 0; }

    const size_t base = (size_t)b * A + a;
    for (int c = 0; c < C; c++)
        out_conf[base * C + c] = (lab == c + 1) ? score : 0.f;

    float4 m   = sbox[idx];
    float4 anc = anchors[a];
    float mcx = (m.x + m.z) * 0.5f, mcy = (m.y + m.w) * 0.5f;
    float mw  = m.z - m.x,          mh  = m.w - m.y;
    float d0 = (mcx - anc.x) / anc.z;
    float d1 = (mcy - anc.y) / anc.w;
    float d2 = logf(mw / anc.z);
    float d3 = logf(mh / anc.w);
    float4 dv;
    dv.x = (d0 - __ldg(&enc_mean[0])) / __ldg(&enc_std[0]);
    dv.y = (d1 - __ldg(&enc_mean[1])) / __ldg(&enc_std[1]);
    dv.z = (d2 - __ldg(&enc_mean[2])) / __ldg(&enc_std[2]);
    dv.w = (d3 - __ldg(&enc_mean[3])) / __ldg(&enc_std[3]);
    out_delta[base] = dv;
}

extern "C" void kernel_launch(void* const* d_in, const int* in_sizes, int n_in,
                              void* d_out, int out_size)
{
    const float* anchors = (const float*)d_in[0];
    const int*   labels  = (const int*)d_in[1];
    const float* bboxes  = (const float*)d_in[2];
    const float* emean   = (const float*)d_in[3];
    const float* estd    = (const float*)d_in[4];
    const float* thr     = (const float*)d_in[5];

    const int A  = in_sizes[0] / 4;          // anchors [A,4]
    const int BN = in_sizes[1];              // labels [B,N]
    // out = conf [B,A,C] ++ deltas [B,A,4]; with C=1 (num_classes=1): out = B*A*5
    int B = out_size / (5 * A);
    if (B <= 0) B = 1;
    const int N = BN / B;
    const int C = (int)((long)out_size / ((long)B * A)) - 4;

    const int numChunks = (A + TPB - 1) / TPB;
    dim3 grid(numChunks, B);

    k_phase1<<<grid, TPB>>>((const float4*)anchors, (const float4*)bboxes, A, N, numChunks);
    k_phase2<<<B * N, TPB>>>(A, N, numChunks);

    float*  out_conf  = (float*)d_out;
    float4* out_delta = (float4*)((float*)d_out + (size_t)B * A * C);
    k_phase3<<<grid, TPB>>>((const float4*)anchors, (const float4*)bboxes, labels,
                            emean, estd, thr, out_conf, out_delta, A, N, C);
}

// round 2
// speedup vs baseline: 1.3867x; 1.3867x over previous
#include <cuda_runtime.h>

#define TPB 256
#define APT 2                 // anchors per thread
#define CHUNK (TPB * APT)     // anchors per block = 512
#define MAXN 128              // max gt boxes per image supported

// Scratch (device globals; no allocation allowed)
__device__ unsigned long long g_partial[1 << 19];  // per-(b,n) per-chunk best keys
__device__ unsigned long long g_abest[1 << 20];    // per-(b,a) packed (iou, box idx)
__device__ int                g_winner[1 << 20];   // per-(b,a) segment_max winner
__device__ float              g_miou[8192];        // per-(b,n) max iou over anchors

// K1: for each (batch, 512-anchor chunk): compute all IoUs vs N boxes once.
//  - per-anchor best (axis=1 argmax, strict > = first occurrence) -> g_abest
//  - per-box block-best (axis=0 argmax candidate, tie -> lowest anchor) -> g_partial
//  - init g_winner = -1
__global__ void __launch_bounds__(TPB)
k_phase1(const float4* __restrict__ anchors, const float4* __restrict__ bboxes,
         int A, int N, int numChunks)
{
    __shared__ float4 sbox[MAXN];
    __shared__ float  sarea[MAXN];
    __shared__ unsigned long long swb[MAXN * 8];

    const int b = blockIdx.y, chunk = blockIdx.x, tid = threadIdx.x;
    const int lane = tid & 31, wid = tid >> 5;

    for (int n = tid; n < N; n += TPB) {
        float4 bb = bboxes[b * N + n];
        sbox[n] = bb;
        sarea[n] = (bb.z - bb.x) * (bb.w - bb.y);
    }
    __syncthreads();

    const int a0 = chunk * CHUNK + tid;
    const int a1 = a0 + TPB;
    const bool v0 = (a0 < A), v1 = (a1 < A);

    float ax1a = 0.f, ay1a = 0.f, ax2a = 0.f, ay2a = 0.f, areaA0 = 0.f;
    float ax1b = 0.f, ay1b = 0.f, ax2b = 0.f, ay2b = 0.f, areaA1 = 0.f;
    if (v0) {
        float4 c = anchors[a0];
        ax1a = c.x - c.z * 0.5f;  ay1a = c.y - c.w * 0.5f;
        ax2a = c.x + c.z * 0.5f;  ay2a = c.y + c.w * 0.5f;
        areaA0 = (ax2a - ax1a) * (ay2a - ay1a);      // matches reference order
        g_winner[(size_t)b * A + a0] = -1;
    }
    if (v1) {
        float4 c = anchors[a1];
        ax1b = c.x - c.z * 0.5f;  ay1b = c.y - c.w * 0.5f;
        ax2b = c.x + c.z * 0.5f;  ay2b = c.y + c.w * 0.5f;
        areaA1 = (ax2b - ax1b) * (ay2b - ay1b);
        g_winner[(size_t)b * A + a1] = -1;
    }

    float bestI0 = -1.0f, bestI1 = -1.0f;
    int   bestN0 = 0,     bestN1 = 0;

    for (int n = 0; n < N; n++) {
        float4 bb = sbox[n];
        float sa = sarea[n];

        // IoU for anchor a0
        float ltx = fmaxf(ax1a, bb.x), lty = fmaxf(ay1a, bb.y);
        float rbx = fminf(ax2a, bb.z), rby = fminf(ay2a, bb.w);
        float w = fmaxf(rbx - ltx, 0.f), h = fmaxf(rby - lty, 0.f);
        float inter = w * h;
        float iou0 = inter / (areaA0 + sa - inter);
        if (!v0) iou0 = -1.0f;

        // IoU for anchor a1
        float ltx2 = fmaxf(ax1b, bb.x), lty2 = fmaxf(ay1b, bb.y);
        float rbx2 = fminf(ax2b, bb.z), rby2 = fminf(ay2b, bb.w);
        float w2 = fmaxf(rbx2 - ltx2, 0.f), h2 = fmaxf(rby2 - lty2, 0.f);
        float inter2 = w2 * h2;
        float iou1 = inter2 / (areaA1 + sa - inter2);
        if (!v1) iou1 = -1.0f;

        // per-anchor running argmax (strict > = first occurrence)
        if (iou0 > bestI0) { bestI0 = iou0; bestN0 = n; }
        if (iou1 > bestI1) { bestI1 = iou1; bestN1 = n; }

        // local merge of the two anchors (tie -> lower anchor index = a0)
        float mi = (iou1 > iou0) ? iou1 : iou0;
        unsigned wa = (iou1 > iou0) ? (unsigned)a1 : (unsigned)a0;

        // warp argmax over anchors for this box: max IoU, tie -> min anchor
        unsigned u = (mi >= 0.f) ? __float_as_uint(mi) : 0u;
        unsigned m = __reduce_max_sync(0xffffffffu, u);
        unsigned cand = (u == m && mi >= 0.f) ? wa : 0xFFFFFFFFu;
        unsigned amin = __reduce_min_sync(0xffffffffu, cand);
        if (lane == 0)
            swb[n * 8 + wid] =
                ((unsigned long long)m << 32) | (0xFFFFFFFFu - amin);
    }

    if (v0)
        g_abest[(size_t)b * A + a0] =
            ((unsigned long long)__float_as_uint(bestI0) << 32) | (unsigned)bestN0;
    if (v1)
        g_abest[(size_t)b * A + a1] =
            ((unsigned long long)__float_as_uint(bestI1) << 32) | (unsigned)bestN1;

    __syncthreads();
    for (int n = tid; n < N; n += TPB) {
        unsigned long long best = swb[n * 8];
        #pragma unroll
        for (int w8 = 1; w8 < 8; w8++)
            if (swb[n * 8 + w8] > best) best = swb[n * 8 + w8];
        g_partial[((size_t)(b * N + n)) * numChunks + chunk] = best;
    }
}

// K2: reduce chunk partials per (b,n) -> max_iou_of_bbox + anchor argmax,
//     then segment_max scatter: winner[anchor] = max n claiming it.
__global__ void __launch_bounds__(TPB)
k_phase2(int A, int N, int numChunks)
{
    const int bn = blockIdx.x, tid = threadIdx.x;
    const int lane = tid & 31, wid = tid >> 5;
    const unsigned long long* p = g_partial + (size_t)bn * numChunks;

    unsigned long long key = 0;
    for (int c = tid; c < numChunks; c += TPB) {
        unsigned long long v = p[c];
        if (v > key) key = v;
    }
    __shared__ unsigned long long sred[8];
    #pragma unroll
    for (int off = 16; off; off >>= 1) {
        unsigned long long o = __shfl_down_sync(0xffffffffu, key, off);
        if (o > key) key = o;
    }
    if (lane == 0) sred[wid] = key;
    __syncthreads();
    if (wid == 0) {
        key = (lane < 8) ? sred[lane] : 0ull;
        #pragma unroll
        for (int off = 4; off; off >>= 1) {
            unsigned long long o = __shfl_down_sync(0xffffffffu, key, off);
            if (o > key) key = o;
        }
        if (lane == 0) {
            float miou = __uint_as_float((unsigned)(key >> 32));
            int   idx  = (int)(0xFFFFFFFFu - (unsigned)key);
            g_miou[bn] = miou;
            int b = bn / N, n = bn - b * N;
            atomicMax(&g_winner[(size_t)b * A + idx], n);
        }
    }
}

// K3: epilogue per anchor: winner override, scores, conf scatter, delta encode.
__global__ void __launch_bounds__(TPB)
k_phase3(const float4* __restrict__ anchors, const float4* __restrict__ bboxes,
         const int* __restrict__ labels,
         const float* __restrict__ enc_mean, const float* __restrict__ enc_std,
         const float* __restrict__ thr_ptr,
         float* __restrict__ out_conf, float4* __restrict__ out_delta,
         int A, int N, int C)
{
    __shared__ float4 sbox[MAXN];
    __shared__ int    slab[MAXN];
    __shared__ float  smiou[MAXN];

    const int b = blockIdx.y, tid = threadIdx.x;
    for (int n = tid; n < N; n += TPB) {
        sbox[n]  = bboxes[b * N + n];
        slab[n]  = labels[b * N + n];
        smiou[n] = g_miou[b * N + n];
    }
    __syncthreads();

    const int a = blockIdx.x * TPB + tid;
    if (a >= A) return;

    const float thr = __ldg(thr_ptr);
    unsigned long long ab = g_abest[(size_t)b * A + a];
    float miou = __uint_as_float((unsigned)(ab >> 32));
    int   idx  = (int)(unsigned)ab;

    int w = g_winner[(size_t)b * A + a];
    if (w >= 0) { idx = w; miou = smiou[w]; }

    float den = fmaxf(smiou[idx], thr);
    if (miou < thr * 0.5f) miou = 0.f;
    float score = miou / den;

    int lab = slab[idx];
    if (lab <= 0) { score = 0.f; lab = 0; }

    const size_t base = (size_t)b * A + a;
    for (int c = 0; c < C; c++)
        out_conf[base * C + c] = (lab == c + 1) ? score : 0.f;

    float4 m   = sbox[idx];
    float4 anc = anchors[a];
    float mcx = (m.x + m.z) * 0.5f, mcy = (m.y + m.w) * 0.5f;
    float mw  = m.z - m.x,          mh  = m.w - m.y;
    float d0 = (mcx - anc.x) / anc.z;
    float d1 = (mcy - anc.y) / anc.w;
    float d2 = logf(mw / anc.z);
    float d3 = logf(mh / anc.w);
    float4 dv;
    dv.x = (d0 - __ldg(&enc_mean[0])) / __ldg(&enc_std[0]);
    dv.y = (d1 - __ldg(&enc_mean[1])) / __ldg(&enc_std[1]);
    dv.z = (d2 - __ldg(&enc_mean[2])) / __ldg(&enc_std[2]);
    dv.w = (d3 - __ldg(&enc_mean[3])) / __ldg(&enc_std[3]);
    out_delta[base] = dv;
}

extern "C" void kernel_launch(void* const* d_in, const int* in_sizes, int n_in,
                              void* d_out, int out_size)
{
    const float* anchors = (const float*)d_in[0];
    const int*   labels  = (const int*)d_in[1];
    const float* bboxes  = (const float*)d_in[2];
    const float* emean   = (const float*)d_in[3];
    const float* estd    = (const float*)d_in[4];
    const float* thr     = (const float*)d_in[5];

    const int A  = in_sizes[0] / 4;          // anchors [A,4]
    const int BN = in_sizes[1];              // labels [B,N]
    // out = conf [B,A,C] ++ deltas [B,A,4]; with C=1 (num_classes=1): out = B*A*5
    int B = out_size / (5 * A);
    if (B <= 0) B = 1;
    const int N = BN / B;
    const int C = (int)((long)out_size / ((long)B * A)) - 4;

    const int numChunks = (A + CHUNK - 1) / CHUNK;
    dim3 grid1(numChunks, B);

    k_phase1<<<grid1, TPB>>>((const float4*)anchors, (const float4*)bboxes, A, N, numChunks);
    k_phase2<<<B * N, TPB>>>(A, N, numChunks);

    float*  out_conf  = (float*)d_out;
    float4* out_delta = (float4*)((float*)d_out + (size_t)B * A * C);
    dim3 grid3((A + TPB - 1) / TPB, B);
    k_phase3<<<grid3, TPB>>>((const float4*)anchors, (const float4*)bboxes, labels,
                             emean, estd, thr, out_conf, out_delta, A, N, C);
}

// round 3
// speedup vs baseline: 2.9525x; 2.1291x over previous
#include <cuda_runtime.h>

#define TPB 128
#define APT 4                 // anchors per thread
#define CHUNK (TPB * APT)     // anchors per block = 512
#define NW   (TPB / 32)       // warps per block
#define MAXN 128              // max gt boxes per image supported

// Scratch (device globals; no allocation allowed)
__device__ unsigned long long g_partial[1 << 19];  // per-(b,n) per-chunk best keys
__device__ unsigned long long g_abest[1 << 20];    // per-(b,a) packed (iou, box idx)
__device__ int                g_winner[1 << 20];   // per-(b,a) segment_max winner
__device__ float              g_miou[8192];        // per-(b,n) max iou over anchors

// K1: for each (batch, 512-anchor chunk): compute all IoUs vs N boxes once.
//  - per-anchor best (axis=1 argmax, strict > = first occurrence) -> g_abest
//  - per-box block-best (axis=0 argmax candidate, tie -> lowest anchor) -> g_partial
//  - init g_winner = -1
__global__ void __launch_bounds__(TPB)
k_phase1(const float4* __restrict__ anchors, const float4* __restrict__ bboxes,
         int A, int N, int numChunks)
{
    __shared__ float4 sbox[MAXN];
    __shared__ float  sarea[MAXN];
    __shared__ unsigned long long swb[MAXN * NW];

    const int b = blockIdx.y, chunk = blockIdx.x, tid = threadIdx.x;
    const int lane = tid & 31, wid = tid >> 5;

    for (int n = tid; n < N; n += TPB) {
        float4 bb = bboxes[b * N + n];
        sbox[n] = bb;
        sarea[n] = (bb.z - bb.x) * (bb.w - bb.y);
    }
    __syncthreads();

    // Load APT anchors (stride TPB so within-warp anchor order == lane order)
    float ax1[APT], ay1[APT], ax2[APT], ay2[APT], areaA[APT];
    unsigned aidx[APT];
    bool avalid[APT];
    #pragma unroll
    for (int k = 0; k < APT; k++) {
        int a = chunk * CHUNK + k * TPB + tid;
        aidx[k] = (unsigned)a;
        avalid[k] = (a < A);
        if (avalid[k]) {
            float4 c = anchors[a];
            ax1[k] = c.x - c.z * 0.5f;  ay1[k] = c.y - c.w * 0.5f;
            ax2[k] = c.x + c.z * 0.5f;  ay2[k] = c.y + c.w * 0.5f;
            areaA[k] = (ax2[k] - ax1[k]) * (ay2[k] - ay1[k]);  // reference order
            g_winner[(size_t)b * A + a] = -1;
        } else {
            // dummy: IoU is exactly 0 vs any valid box; index larger than all
            // real anchors so it never wins a tie-break.
            ax1[k] = 0.f; ay1[k] = 0.f; ax2[k] = 0.f; ay2[k] = 0.f;
            areaA[k] = 0.f;
        }
    }

    float bestI[APT];
    int   bestN[APT];
    #pragma unroll
    for (int k = 0; k < APT; k++) { bestI[k] = -1.0f; bestN[k] = 0; }

    for (int n = 0; n < N; n++) {
        float4 bb = sbox[n];
        float sa = sarea[n];

        float iou[APT];
        #pragma unroll
        for (int k = 0; k < APT; k++) {
            float ltx = fmaxf(ax1[k], bb.x), lty = fmaxf(ay1[k], bb.y);
            float rbx = fminf(ax2[k], bb.z), rby = fminf(ay2[k], bb.w);
            float w = fmaxf(rbx - ltx, 0.f), h = fmaxf(rby - lty, 0.f);
            float inter = w * h;
            iou[k] = __fdividef(inter, areaA[k] + sa - inter);
        }

        // per-anchor running argmax (strict > = first occurrence)
        #pragma unroll
        for (int k = 0; k < APT; k++)
            if (iou[k] > bestI[k]) { bestI[k] = iou[k]; bestN[k] = n; }

        // merge the APT anchors (strict > keeps earlier = lower anchor index)
        float    mi = iou[0];
        unsigned wa = aidx[0];
        #pragma unroll
        for (int k = 1; k < APT; k++)
            if (iou[k] > mi) { mi = iou[k]; wa = aidx[k]; }

        // warp argmax over anchors for this box: max IoU, tie -> min anchor.
        // IoU >= 0 so float bits are uint-monotone.
        unsigned u = __float_as_uint(mi);
        unsigned m = __reduce_max_sync(0xffffffffu, u);
        unsigned cand = (u == m) ? wa : 0xFFFFFFFFu;
        unsigned amin = __reduce_min_sync(0xffffffffu, cand);
        if (lane == 0)
            swb[n * NW + wid] =
                ((unsigned long long)m << 32) | (0xFFFFFFFFu - amin);
    }

    #pragma unroll
    for (int k = 0; k < APT; k++)
        if (avalid[k])
            g_abest[(size_t)b * A + aidx[k]] =
                ((unsigned long long)__float_as_uint(bestI[k]) << 32) |
                (unsigned)bestN[k];

    __syncthreads();
    for (int n = tid; n < N; n += TPB) {
        unsigned long long best = swb[n * NW];
        #pragma unroll
        for (int w8 = 1; w8 < NW; w8++)
            if (swb[n * NW + w8] > best) best = swb[n * NW + w8];
        g_partial[((size_t)(b * N + n)) * numChunks + chunk] = best;
    }
}

// K2: reduce chunk partials per (b,n) -> max_iou_of_bbox + anchor argmax,
//     then segment_max scatter: winner[anchor] = max n claiming it.
__global__ void __launch_bounds__(256)
k_phase2(int A, int N, int numChunks)
{
    const int bn = blockIdx.x, tid = threadIdx.x;
    const int lane = tid & 31, wid = tid >> 5;
    const unsigned long long* p = g_partial + (size_t)bn * numChunks;

    unsigned long long key = 0;
    for (int c = tid; c < numChunks; c += 256) {
        unsigned long long v = p[c];
        if (v > key) key = v;
    }
    __shared__ unsigned long long sred[8];
    #pragma unroll
    for (int off = 16; off; off >>= 1) {
        unsigned long long o = __shfl_down_sync(0xffffffffu, key, off);
        if (o > key) key = o;
    }
    if (lane == 0) sred[wid] = key;
    __syncthreads();
    if (wid == 0) {
        key = (lane < 8) ? sred[lane] : 0ull;
        #pragma unroll
        for (int off = 4; off; off >>= 1) {
            unsigned long long o = __shfl_down_sync(0xffffffffu, key, off);
            if (o > key) key = o;
        }
        if (lane == 0) {
            float miou = __uint_as_float((unsigned)(key >> 32));
            int   idx  = (int)(0xFFFFFFFFu - (unsigned)key);
            g_miou[bn] = miou;
            int b = bn / N, n = bn - b * N;
            atomicMax(&g_winner[(size_t)b * A + idx], n);
        }
    }
}

// K3: epilogue per anchor: winner override, scores, conf scatter, delta encode.
__global__ void __launch_bounds__(256)
k_phase3(const float4* __restrict__ anchors, const float4* __restrict__ bboxes,
         const int* __restrict__ labels,
         const float* __restrict__ enc_mean, const float* __restrict__ enc_std,
         const float* __restrict__ thr_ptr,
         float* __restrict__ out_conf, float4* __restrict__ out_delta,
         int A, int N, int C)
{
    __shared__ float4 sbox[MAXN];
    __shared__ int    slab[MAXN];
    __shared__ float  smiou[MAXN];

    const int b = blockIdx.y, tid = threadIdx.x;
    for (int n = tid; n < N; n += 256) {
        sbox[n]  = bboxes[b * N + n];
        slab[n]  = labels[b * N + n];
        smiou[n] = g_miou[b * N + n];
    }
    __syncthreads();

    const int a = blockIdx.x * 256 + tid;
    if (a >= A) return;

    const float thr = __ldg(thr_ptr);
    unsigned long long ab = g_abest[(size_t)b * A + a];
    float miou = __uint_as_float((unsigned)(ab >> 32));
    int   idx  = (int)(unsigned)ab;

    int w = g_winner[(size_t)b * A + a];
    if (w >= 0) { idx = w; miou = smiou[w]; }

    float den = fmaxf(smiou[idx], thr);
    if (miou < thr * 0.5f) miou = 0.f;
    float score = miou / den;

    int lab = slab[idx];
    if (lab <= 0) { score = 0.f; lab = 0; }

    const size_t base = (size_t)b * A + a;
    for (int c = 0; c < C; c++)
        out_conf[base * C + c] = (lab == c + 1) ? score : 0.f;

    float4 m   = sbox[idx];
    float4 anc = anchors[a];
    float mcx = (m.x + m.z) * 0.5f, mcy = (m.y + m.w) * 0.5f;
    float mw  = m.z - m.x,          mh  = m.w - m.y;
    float d0 = (mcx - anc.x) / anc.z;
    float d1 = (mcy - anc.y) / anc.w;
    float d2 = logf(mw / anc.z);
    float d3 = logf(mh / anc.w);
    float4 dv;
    dv.x = (d0 - __ldg(&enc_mean[0])) / __ldg(&enc_std[0]);
    dv.y = (d1 - __ldg(&enc_mean[1])) / __ldg(&enc_std[1]);
    dv.z = (d2 - __ldg(&enc_mean[2])) / __ldg(&enc_std[2]);
    dv.w = (d3 - __ldg(&enc_mean[3])) / __ldg(&enc_std[3]);
    out_delta[base] = dv;
}

extern "C" void kernel_launch(void* const* d_in, const int* in_sizes, int n_in,
                              void* d_out, int out_size)
{
    const float* anchors = (const float*)d_in[0];
    const int*   labels  = (const int*)d_in[1];
    const float* bboxes  = (const float*)d_in[2];
    const float* emean   = (const float*)d_in[3];
    const float* estd    = (const float*)d_in[4];
    const float* thr     = (const float*)d_in[5];

    const int A  = in_sizes[0] / 4;          // anchors [A,4]
    const int BN = in_sizes[1];              // labels [B,N]
    // out = conf [B,A,C] ++ deltas [B,A,4]; with C=1 (num_classes=1): out = B*A*5
    int B = out_size / (5 * A);
    if (B <= 0) B = 1;
    const int N = BN / B;
    const int C = (int)((long)out_size / ((long)B * A)) - 4;

    const int numChunks = (A + CHUNK - 1) / CHUNK;
    dim3 grid1(numChunks, B);

    k_phase1<<<grid1, TPB>>>((const float4*)anchors, (const float4*)bboxes, A, N, numChunks);
    k_phase2<<<B * N, 256>>>(A, N, numChunks);

    float*  out_conf  = (float*)d_out;
    float4* out_delta = (float4*)((float*)d_out + (size_t)B * A * C);
    dim3 grid3((A + 255) / 256, B);
    k_phase3<<<grid3, 256>>>((const float4*)anchors, (const float4*)bboxes, labels,
                             emean, estd, thr, out_conf, out_delta, A, N, C);
}